// round 2
// baseline (speedup 1.0000x reference)
#include <cuda_runtime.h>
#include <cuda_bf16.h>
#include <math.h>

#define D       512
#define NTOK    4096      // B*SLEN = 4*1024
#define NNODn   8
#define NEDGEn  34
#define EPSf    1e-6f

#define BM 128
#define BN 64
#define BK 16

// ---------------- scratch buffers (device globals; no allocation allowed) ----------
__device__ float g_outs[8][NTOK * D];
__device__ float g_q[NTOK * D];
__device__ float g_k[NTOK * D];
__device__ float g_v[NTOK * D];
__device__ float g_t1[NTOK * D];
__device__ float g_t2[NTOK * D];
__device__ float g_t3[NTOK * D];
__device__ float g_t4[NTOK * D];

// ---------------- descriptors ----------------
struct GemmDesc {
    int active;
    int pre_mode;    // 0 none, 1 LN(A), 2 relu(A)
    int epi_act;     // 0 none, 1 relu, 2 gelu
    int accumulate;  // 1: C += result
    const float *A, *W, *bias, *lng, *lnb, *mult, *residual;
    float scale;
    float *C;
};
struct CopyDesc { int active; const float* src; float* dst; float scale; };
struct ElemDesc {
    int active; int opcode;   // 2,4,6,7
    const float *q, *k, *v, *g, *b;
    float scale; float* dst;
};

__device__ GemmDesc g_gd[56];   // node*7 + {EQ,EK,EV,G1,G2,G3,G4}
__device__ CopyDesc g_cd[24];   // node*3 + {q,k,v}
__device__ ElemDesc g_ed[8];
__device__ int g_attn_on[8];
__device__ int g_rem_mask;

// ---------------- small helpers ----------------
__device__ __forceinline__ float gelu_f(float x) {
    const float k0 = 0.7978845608028654f;
    float x3 = x * x * x;
    return 0.5f * x * (1.f + tanhf(k0 * (x + 0.044715f * x3)));
}

__device__ float selw_masked(const float* l, int L, int mask5, int sel) {
    float mx = -1e30f;
    for (int i = 0; i < L; i++) { if (mask5 && i < 5) continue; if (l[i] > mx) mx = l[i]; }
    float s = 0.f;
    for (int i = 0; i < L; i++) { if (mask5 && i < 5) continue; s += expf(l[i] - mx); }
    return expf(l[sel] - mx) / s;
}

__device__ void set_gd(int slot, const float* A, const float* W, const float* bias,
                       int pre, const float* lng, const float* lnb,
                       int epi, const float* mult, const float* residual,
                       float scale, float* C, int accum) {
    GemmDesc& g = g_gd[slot];
    g.active = 1; g.A = A; g.W = W; g.bias = bias;
    g.pre_mode = pre; g.lng = lng; g.lnb = lnb;
    g.epi_act = epi; g.mult = mult; g.residual = residual;
    g.scale = scale; g.C = C; g.accumulate = accum;
}

// Fill an edge slot; returns consumed input node index inn (-2..7)
__device__ int fill_edge(int node, int which, int sel, float w, int lind, int snode,
                         const float* const* bufs,
                         const float* eW, const float* eb, const float* eg, const float* ebe,
                         float* dst) {
    int se = sel / 5, op = sel % 5;
    int inn = (se == 0) ? -2 : (snode + se);
    int e = lind + se;
    const float* src = bufs[inn + 2];
    if (op == 4) {
        CopyDesc& cd = g_cd[node * 3 + which];
        cd.active = 1; cd.src = src; cd.dst = dst; cd.scale = w;
    } else {
        set_gd(node * 7 + which,
               src, eW + (size_t)e * D * D, eb + e * D,
               (op <= 2) ? 1 : 0, eg + e * D, ebe + e * D,
               (op == 0) ? 1 : ((op == 1) ? 2 : 0),
               nullptr, nullptr, w, dst, 0);
    }
    return inn;
}

// ---------------- routing kernel: computes routes + writes all descriptors ----------
__global__ void routing_kernel(const float* inpute, const float* inputo,
                               const float* node_p, const float* edge_p,
                               const float* edge_W, const float* edge_b,
                               const float* edge_g, const float* edge_beta,
                               const float* node_W, const float* node_b,
                               const float* node_g, const float* node_beta) {
    if (threadIdx.x != 0 || blockIdx.x != 0) return;

    const float* bufs[10];
    bufs[0] = inpute; bufs[1] = inputo;
    for (int i = 0; i < 8; i++) bufs[2 + i] = g_outs[i];

    for (int i = 0; i < 56; i++) g_gd[i].active = 0;
    for (int i = 0; i < 24; i++) g_cd[i].active = 0;
    for (int i = 0; i < 8; i++) { g_ed[i].active = 0; g_attn_on[i] = 0; }

    int processed = 0;
    int lind = 0;
    for (int c = 0; c < 8; c++) {
        int nsrc = (c + 2 < 5) ? (c + 2) : 5;
        int snode = c - nsrc;
        int L = nsrc * 5;
        float ep0[25], ep1[25], ep2[25];
        for (int s = 0; s < nsrc; s++)
            for (int j = 0; j < 5; j++) {
                int e = lind + s;
                ep0[s * 5 + j] = edge_p[(0 * NEDGEn + e) * 5 + j];
                ep1[s * 5 + j] = edge_p[(1 * NEDGEn + e) * 5 + j];
                ep2[s * 5 + j] = edge_p[(2 * NEDGEn + e) * 5 + j];
            }
        // node activation argmax + softmax weight
        int nact = 0; float bb = node_p[c * 8];
        for (int i = 1; i < 8; i++) { float x = node_p[c * 8 + i]; if (x > bb) { bb = x; nact = i; } }
        float aw;
        { float sum = 0.f; for (int i = 0; i < 8; i++) sum += expf(node_p[c * 8 + i] - bb);
          aw = expf(node_p[c * 8 + nact] - bb) / sum; }

        // q selection: first 5 masked
        int qsel = 5; float qb = ep0[5];
        for (int i = 6; i < L; i++) if (ep0[i] > qb) { qb = ep0[i]; qsel = i; }
        float wq = selw_masked(ep0, L, 1, qsel);

        int ksel = -1, vsel = -1, vfirst5 = 0;
        float wk = 0.f, wv = 0.f;
        int ktype = 0;
        if (nact < 7) {
            int km = (nact > 0) ? 1 : 0;
            int start = km ? 5 : 0;
            ksel = start; float kb = ep1[start];
            for (int i = start + 1; i < L; i++) if (ep1[i] > kb) { kb = ep1[i]; ksel = i; }
            wk = selw_masked(ep1, L, km, ksel);
            ktype = (ksel / 5 == 0) ? -2 : -1;
            if (nact < 5) {
                if (nact == 0 && ktype == -2) {
                    vfirst5 = 1;
                    vsel = 0; float vb = ep2[0];
                    for (int i = 1; i < 5; i++) if (ep2[i] > vb) { vb = ep2[i]; vsel = i; }
                    wv = selw_masked(ep2, 5, 0, vsel);
                } else {
                    int vm = km;
                    int vstart = vm ? 5 : 0;
                    vsel = vstart; float vb = ep2[vstart];
                    for (int i = vstart + 1; i < L; i++) if (ep2[i] > vb) { vb = ep2[i]; vsel = i; }
                    wv = selw_masked(ep2, L, vm, vsel);
                }
            }
        }

        // edge descriptors
        float* outc = g_outs[c];
        int inn;
        inn = fill_edge(c, 0, qsel, wq, lind, snode, bufs, edge_W, edge_b, edge_g, edge_beta, g_q);
        processed |= 1 << (inn + 2);
        if (nact < 7) {
            inn = fill_edge(c, 1, ksel, wk, lind, snode, bufs, edge_W, edge_b, edge_g, edge_beta, g_k);
            processed |= 1 << (inn + 2);
        }
        if (nact < 5) {
            inn = fill_edge(c, 2, vsel, wv, lind, snode, bufs, edge_W, edge_b, edge_g, edge_beta, g_v);
            processed |= 1 << (inn + 2);
        }

        // node descriptors
        const float* nw  = node_W + (size_t)c * 4 * D * D;
        const float* nbv = node_b + (size_t)c * 4 * D;
        const float* ngv = node_g + (size_t)c * D;
        const float* nbe = node_beta + (size_t)c * D;
        int s3 = c * 7 + 3, s4 = c * 7 + 4, s5 = c * 7 + 5, s6 = c * 7 + 6;

        if (nact == 0) {
            set_gd(s3, g_q, nw,             nbv,         1, ngv, nbe, 0, nullptr, nullptr, 1.f, g_t1, 0);
            set_gd(s4, g_k, nw + D * D,     nbv + D,     0, nullptr, nullptr, 0, nullptr, nullptr, 1.f, g_t2, 0);
            set_gd(s5, g_v, nw + 2 * D * D, nbv + 2 * D, 0, nullptr, nullptr, 0, nullptr, nullptr, 1.f, g_t3, 0);
            g_attn_on[c] = 1;
            set_gd(s6, g_t4, nw + 3 * D * D, nbv + 3 * D, 0, nullptr, nullptr, 0, nullptr, g_q, aw, outc, 0);
        } else if (nact == 1) {
            set_gd(s3, g_q, nw,         nbv,     0, nullptr, nullptr, 2, nullptr, nullptr, 1.f, g_t1, 0);
            set_gd(s4, g_k, nw + D * D, nbv + D, 0, nullptr, nullptr, 0, g_t1, nullptr, 1.f, g_t4, 0);
            set_gd(s6, g_t4, nw + 3 * D * D, nbv + 3 * D, 0, nullptr, nullptr, 0, nullptr, g_q, aw, outc, 0);
        } else if (nact == 3) {
            set_gd(s3, g_q, nw,             nullptr, 0, nullptr, nullptr, 0, nullptr, nullptr, 1.f, g_t1, 0);
            set_gd(s4, g_k, nw + D * D,     nullptr, 0, nullptr, nullptr, 0, nullptr, nullptr, 1.f, g_t1, 1);
            set_gd(s5, g_v, nw + 2 * D * D, nullptr, 0, nullptr, nullptr, 0, nullptr, nullptr, 1.f, g_t1, 1);
            set_gd(s6, g_t1, nw + 3 * D * D, nbv + 3 * D, 2, nullptr, nullptr, 0, nullptr, g_q, aw, outc, 0);
        } else if (nact == 5) {
            set_gd(s4, g_k, nw + D * D, nbv + D, 0, nullptr, nullptr, 2, nullptr, g_q, aw, outc, 0);
        } else { // 2, 4, 6, 7 elementwise
            ElemDesc& e = g_ed[c];
            e.active = 1; e.opcode = nact;
            e.q = g_q; e.k = g_k; e.v = g_v;
            e.g = ngv; e.b = nbe; e.scale = aw; e.dst = outc;
        }
        lind += nsrc;
    }
    int rem = 0;
    for (int n = 0; n < 8; n++)
        if (!((processed >> (n + 2)) & 1)) rem |= 1 << n;
    g_rem_mask = rem;
}

// ---------------- generic GEMM slot kernel ----------------
// C[NTOK,D] = epi( pre(A)[NTOK,D] @ W[D,D] + bias ) (*mult)(+residual)(*scale)
__global__ __launch_bounds__(256) void gemm_slot(int slot) {
    GemmDesc d = g_gd[slot];
    if (!d.active) return;

    __shared__ float sA[BK][BM + 4];
    __shared__ float sW[BK][BN + 4];
    __shared__ float s_mean[BM], s_rstd[BM];
    __shared__ float red_s[256], red_q[256];

    int tid = threadIdx.x;
    int m0 = blockIdx.y * BM;
    int n0 = blockIdx.x * BN;

    if (d.pre_mode == 1) {
        int r = tid >> 1, p = tid & 1;
        const float* row = d.A + (size_t)(m0 + r) * D + p * 256;
        float s = 0.f, ss = 0.f;
        #pragma unroll 8
        for (int i = 0; i < 256; i++) { float a = row[i]; s += a; ss += a * a; }
        red_s[tid] = s; red_q[tid] = ss;
        __syncthreads();
        if (p == 0) {
            float S = red_s[tid] + red_s[tid + 1];
            float Q = red_q[tid] + red_q[tid + 1];
            float m = S * (1.f / 512.f);
            float var = Q * (1.f / 512.f) - m * m;
            s_mean[r] = m; s_rstd[r] = rsqrtf(var + EPSf);
        }
        __syncthreads();
    }

    float acc[8][4];
    #pragma unroll
    for (int i = 0; i < 8; i++)
        #pragma unroll
        for (int j = 0; j < 4; j++) acc[i][j] = 0.f;

    int ty = tid >> 4, tx = tid & 15;   // ty:0..15 -> 8 rows each; tx:0..15 -> 4 cols each

    for (int k0 = 0; k0 < D; k0 += BK) {
        #pragma unroll
        for (int i = 0; i < 8; i++) {
            int idx = tid + i * 256;           // 2048 = 128*16
            int am = idx >> 4, ak = idx & 15;
            float a = d.A[(size_t)(m0 + am) * D + k0 + ak];
            if (d.pre_mode == 1)
                a = (a - s_mean[am]) * s_rstd[am] * d.lng[k0 + ak] + d.lnb[k0 + ak];
            else if (d.pre_mode == 2)
                a = fmaxf(a, 0.f);
            sA[ak][am] = a;
        }
        #pragma unroll
        for (int i = 0; i < 4; i++) {
            int idx = tid + i * 256;           // 1024 = 16*64
            int wn = idx & 63, wk = idx >> 6;
            sW[wk][wn] = d.W[(size_t)(k0 + wk) * D + n0 + wn];
        }
        __syncthreads();
        #pragma unroll
        for (int kk = 0; kk < BK; kk++) {
            float a[8], b[4];
            #pragma unroll
            for (int i = 0; i < 8; i++) a[i] = sA[kk][ty * 8 + i];
            #pragma unroll
            for (int j = 0; j < 4; j++) b[j] = sW[kk][tx * 4 + j];
            #pragma unroll
            for (int i = 0; i < 8; i++)
                #pragma unroll
                for (int j = 0; j < 4; j++) acc[i][j] += a[i] * b[j];
        }
        __syncthreads();
    }

    #pragma unroll
    for (int i = 0; i < 8; i++) {
        int m = m0 + ty * 8 + i;
        #pragma unroll
        for (int j = 0; j < 4; j++) {
            int n = n0 + tx * 4 + j;
            float cv = acc[i][j];
            if (d.bias) cv += d.bias[n];
            if (d.epi_act == 1) cv = fmaxf(cv, 0.f);
            else if (d.epi_act == 2) cv = gelu_f(cv);
            if (d.mult) cv *= d.mult[(size_t)m * D + n];
            if (d.residual) cv += d.residual[(size_t)m * D + n];
            cv *= d.scale;
            if (d.accumulate) d.C[(size_t)m * D + n] += cv;
            else d.C[(size_t)m * D + n] = cv;
        }
    }
}

// ---------------- edge op4 copy-scale ----------------
__global__ void copy_slot(int slot) {
    CopyDesc d = g_cd[slot];
    if (!d.active) return;
    for (int i = blockIdx.x * blockDim.x + threadIdx.x; i < NTOK * D; i += gridDim.x * blockDim.x)
        d.dst[i] = d.scale * d.src[i];
}

// ---------------- attention (act 0): one warp per query row, online softmax ------
__global__ __launch_bounds__(256) void attn_slot(int c) {
    if (!g_attn_on[c]) return;
    int warp = threadIdx.x >> 5, lane = threadIdx.x & 31;
    int bh = blockIdx.x;            // 0..31
    int b = bh >> 3, h = bh & 7;
    int s = blockIdx.y * 8 + warp;  // 0..1023

    const float* qrow = g_t1 + (size_t)((b << 10) + s) * D + h * 64 + lane * 2;
    float q0 = qrow[0], q1 = qrow[1];
    const float* kbase = g_t2 + (size_t)(b << 10) * D + h * 64 + lane * 2;
    const float* vbase = g_t3 + (size_t)(b << 10) * D + h * 64 + lane * 2;

    float m = -1e30f, l = 0.f, a0 = 0.f, a1 = 0.f;
    for (int sk = 0; sk < 1024; sk++) {
        float2 kk = *(const float2*)(kbase + (size_t)sk * D);
        float p = q0 * kk.x + q1 * kk.y;
        p += __shfl_xor_sync(0xFFFFFFFFu, p, 16);
        p += __shfl_xor_sync(0xFFFFFFFFu, p, 8);
        p += __shfl_xor_sync(0xFFFFFFFFu, p, 4);
        p += __shfl_xor_sync(0xFFFFFFFFu, p, 2);
        p += __shfl_xor_sync(0xFFFFFFFFu, p, 1);
        float dot = p * 0.125f;
        float mn = fmaxf(m, dot);
        float corr = __expf(m - mn);
        float w = __expf(dot - mn);
        float2 vv = *(const float2*)(vbase + (size_t)sk * D);
        l = l * corr + w;
        a0 = a0 * corr + w * vv.x;
        a1 = a1 * corr + w * vv.y;
        m = mn;
    }
    float inv = 1.f / l;
    float* orow = g_t4 + (size_t)((b << 10) + s) * D + h * 64 + lane * 2;
    orow[0] = a0 * inv;
    orow[1] = a1 * inv;
}

// ---------------- elementwise node ops (acts 2,4,6,7) ----------------
__global__ __launch_bounds__(256) void elem_node_kernel(int c) {
    ElemDesc d = g_ed[c];
    if (!d.active) return;
    int row = blockIdx.x;
    int tid = threadIdx.x;
    size_t base = (size_t)row * D;
    float x[2];
    #pragma unroll
    for (int i = 0; i < 2; i++) {
        int j = tid + i * 256;
        float qv = d.q[base + j];
        if (d.opcode == 2) x[i] = qv + d.k[base + j] + d.v[base + j];
        else if (d.opcode == 4) {
            float kv = d.k[base + j];
            x[i] = qv * (1.f / (1.f + expf(-kv))) + d.v[base + j];
        }
        else if (d.opcode == 6) x[i] = qv + d.k[base + j];
        else x[i] = qv; // 7
    }
    if (d.opcode == 2 || d.opcode == 7) {
        __shared__ float rs[256], rq[256];
        rs[tid] = x[0] + x[1];
        rq[tid] = x[0] * x[0] + x[1] * x[1];
        __syncthreads();
        for (int off = 128; off > 0; off >>= 1) {
            if (tid < off) { rs[tid] += rs[tid + off]; rq[tid] += rq[tid + off]; }
            __syncthreads();
        }
        float mean = rs[0] * (1.f / 512.f);
        float var = rq[0] * (1.f / 512.f) - mean * mean;
        float rstd = rsqrtf(var + EPSf);
        #pragma unroll
        for (int i = 0; i < 2; i++) {
            int j = tid + i * 256;
            d.dst[base + j] = d.scale * ((x[i] - mean) * rstd * d.g[j] + d.b[j]);
        }
    } else {
        #pragma unroll
        for (int i = 0; i < 2; i++) {
            int j = tid + i * 256;
            d.dst[base + j] = d.scale * x[i];
        }
    }
}

// ---------------- final: sum remaining outs + LayerNorm ----------------
__global__ __launch_bounds__(256) void final_kernel(const float* out_g, const float* out_beta,
                                                    float* out) {
    int row = blockIdx.x;
    int tid = threadIdx.x;
    int mask = g_rem_mask;
    size_t base = (size_t)row * D;
    float x[2];
    #pragma unroll
    for (int i = 0; i < 2; i++) {
        int j = tid + i * 256;
        float s = 0.f;
        for (int n = 0; n < 8; n++)
            if ((mask >> n) & 1) s += g_outs[n][base + j];
        x[i] = s;
    }
    __shared__ float rs[256], rq[256];
    rs[tid] = x[0] + x[1];
    rq[tid] = x[0] * x[0] + x[1] * x[1];
    __syncthreads();
    for (int off = 128; off > 0; off >>= 1) {
        if (tid < off) { rs[tid] += rs[tid + off]; rq[tid] += rq[tid + off]; }
        __syncthreads();
    }
    float mean = rs[0] * (1.f / 512.f);
    float var = rq[0] * (1.f / 512.f) - mean * mean;
    float rstd = rsqrtf(var + EPSf);
    #pragma unroll
    for (int i = 0; i < 2; i++) {
        int j = tid + i * 256;
        out[base + j] = (x[i] - mean) * rstd * out_g[j] + out_beta[j];
    }
}

// ---------------- launch ----------------
extern "C" void kernel_launch(void* const* d_in, const int* in_sizes, int n_in,
                              void* d_out, int out_size) {
    const float* inpute   = (const float*)d_in[0];
    const float* inputo   = (const float*)d_in[1];
    const float* node_p   = (const float*)d_in[2];
    const float* edge_p   = (const float*)d_in[3];
    const float* edge_W   = (const float*)d_in[4];
    const float* edge_b   = (const float*)d_in[5];
    const float* edge_g   = (const float*)d_in[6];
    const float* edge_bet = (const float*)d_in[7];
    const float* node_W   = (const float*)d_in[8];
    const float* node_b   = (const float*)d_in[9];
    const float* node_g   = (const float*)d_in[10];
    const float* node_bet = (const float*)d_in[11];
    const float* out_g    = (const float*)d_in[12];
    const float* out_bet  = (const float*)d_in[13];
    float* out = (float*)d_out;

    routing_kernel<<<1, 1>>>(inpute, inputo, node_p, edge_p,
                             edge_W, edge_b, edge_g, edge_bet,
                             node_W, node_b, node_g, node_bet);

    dim3 ggrid(D / BN, NTOK / BM);   // (8, 32)
    for (int c = 0; c < 8; c++) {
        for (int w = 0; w < 3; w++) {
            gemm_slot<<<ggrid, 256>>>(c * 7 + w);
            copy_slot<<<1024, 256>>>(c * 3 + w);
        }
        gemm_slot<<<ggrid, 256>>>(c * 7 + 3);
        gemm_slot<<<ggrid, 256>>>(c * 7 + 4);
        gemm_slot<<<ggrid, 256>>>(c * 7 + 5);
        attn_slot<<<dim3(32, 128), 256>>>(c);
        gemm_slot<<<ggrid, 256>>>(c * 7 + 6);
        elem_node_kernel<<<NTOK, 256>>>(c);
    }
    final_kernel<<<NTOK, 256>>>(out_g, out_bet, out);
}

// round 3
// speedup vs baseline: 2.3823x; 2.3823x over previous
#include <cuda_runtime.h>
#include <cuda_bf16.h>
#include <math.h>

#define D       512
#define NTOK    4096      // B*SLEN = 4*1024
#define NNODn   8
#define NEDGEn  34
#define EPSf    1e-6f

// GEMM tile
#define BM 64
#define BN 128
#define BK 16

// ---------------- scratch buffers (device globals; no allocation allowed) ----------
__device__ float g_outs[8][NTOK * D];
__device__ float g_q[NTOK * D];
__device__ float g_k[NTOK * D];
__device__ float g_v[NTOK * D];
__device__ float g_t1[NTOK * D];
__device__ float g_t2[NTOK * D];
__device__ float g_t3[NTOK * D];
__device__ float g_t4[NTOK * D];

// ---------------- descriptors ----------------
struct GemmDesc {
    int active;
    int pre_mode;    // 0 none, 1 LN(A), 2 relu(A)
    int epi_act;     // 0 none, 1 relu, 2 gelu
    int accumulate;  // 1: C += result
    const float *A, *W, *bias, *lng, *lnb, *mult, *residual;
    float scale;
    float *C;
};
struct CopyDesc { int active; const float* src; float* dst; float scale; };
struct ElemDesc {
    int active; int opcode;   // 2,4,6,7
    const float *q, *k, *v, *g, *b;
    float scale; float* dst;
};

__device__ GemmDesc g_gd[56];   // node*7 + {EQ,EK,EV,G1,G2,G3,G4}
__device__ CopyDesc g_cd[24];   // node*3 + {q,k,v}
__device__ ElemDesc g_ed[8];
__device__ int g_attn_on[8];
__device__ int g_rem_mask;

// ---------------- packed f32x2 helpers ----------------
__device__ __forceinline__ unsigned long long pack2(float lo, float hi) {
    unsigned long long r;
    asm("mov.b64 %0, {%1, %2};" : "=l"(r)
        : "r"(__float_as_uint(lo)), "r"(__float_as_uint(hi)));
    return r;
}
__device__ __forceinline__ void fma2(unsigned long long& acc, unsigned long long a,
                                     unsigned long long b) {
    asm("fma.rn.f32x2 %0, %1, %2, %0;" : "+l"(acc) : "l"(a), "l"(b));
}
__device__ __forceinline__ float2 unpack2(unsigned long long v) {
    unsigned lo, hi;
    asm("mov.b64 {%0, %1}, %2;" : "=r"(lo), "=r"(hi) : "l"(v));
    float2 f; f.x = __uint_as_float(lo); f.y = __uint_as_float(hi);
    return f;
}

// ---------------- small helpers ----------------
__device__ __forceinline__ float gelu_f(float x) {
    const float k0 = 0.7978845608028654f;
    float x3 = x * x * x;
    return 0.5f * x * (1.f + tanhf(k0 * (x + 0.044715f * x3)));
}

__device__ float selw_masked(const float* l, int L, int mask5, int sel) {
    float mx = -1e30f;
    for (int i = 0; i < L; i++) { if (mask5 && i < 5) continue; if (l[i] > mx) mx = l[i]; }
    float s = 0.f;
    for (int i = 0; i < L; i++) { if (mask5 && i < 5) continue; s += expf(l[i] - mx); }
    return expf(l[sel] - mx) / s;
}

__device__ void set_gd(int slot, const float* A, const float* W, const float* bias,
                       int pre, const float* lng, const float* lnb,
                       int epi, const float* mult, const float* residual,
                       float scale, float* C, int accum) {
    GemmDesc& g = g_gd[slot];
    g.active = 1; g.A = A; g.W = W; g.bias = bias;
    g.pre_mode = pre; g.lng = lng; g.lnb = lnb;
    g.epi_act = epi; g.mult = mult; g.residual = residual;
    g.scale = scale; g.C = C; g.accumulate = accum;
}

// Fill an edge slot; returns consumed input node index inn (-2..7)
__device__ int fill_edge(int node, int which, int sel, float w, int lind, int snode,
                         const float* const* bufs,
                         const float* eW, const float* eb, const float* eg, const float* ebe,
                         float* dst) {
    int se = sel / 5, op = sel % 5;
    int inn = (se == 0) ? -2 : (snode + se);
    int e = lind + se;
    const float* src = bufs[inn + 2];
    if (op == 4) {
        CopyDesc& cd = g_cd[node * 3 + which];
        cd.active = 1; cd.src = src; cd.dst = dst; cd.scale = w;
    } else {
        set_gd(node * 7 + which,
               src, eW + (size_t)e * D * D, eb + e * D,
               (op <= 2) ? 1 : 0, eg + e * D, ebe + e * D,
               (op == 0) ? 1 : ((op == 1) ? 2 : 0),
               nullptr, nullptr, w, dst, 0);
    }
    return inn;
}

// ---------------- routing kernel: computes routes + writes all descriptors ----------
__global__ void routing_kernel(const float* inpute, const float* inputo,
                               const float* node_p, const float* edge_p,
                               const float* edge_W, const float* edge_b,
                               const float* edge_g, const float* edge_beta,
                               const float* node_W, const float* node_b,
                               const float* node_g, const float* node_beta) {
    if (threadIdx.x != 0 || blockIdx.x != 0) return;

    const float* bufs[10];
    bufs[0] = inpute; bufs[1] = inputo;
    for (int i = 0; i < 8; i++) bufs[2 + i] = g_outs[i];

    for (int i = 0; i < 56; i++) g_gd[i].active = 0;
    for (int i = 0; i < 24; i++) g_cd[i].active = 0;
    for (int i = 0; i < 8; i++) { g_ed[i].active = 0; g_attn_on[i] = 0; }

    int processed = 0;
    int lind = 0;
    for (int c = 0; c < 8; c++) {
        int nsrc = (c + 2 < 5) ? (c + 2) : 5;
        int snode = c - nsrc;
        int L = nsrc * 5;
        float ep0[25], ep1[25], ep2[25];
        for (int s = 0; s < nsrc; s++)
            for (int j = 0; j < 5; j++) {
                int e = lind + s;
                ep0[s * 5 + j] = edge_p[(0 * NEDGEn + e) * 5 + j];
                ep1[s * 5 + j] = edge_p[(1 * NEDGEn + e) * 5 + j];
                ep2[s * 5 + j] = edge_p[(2 * NEDGEn + e) * 5 + j];
            }
        // node activation argmax + softmax weight
        int nact = 0; float bb = node_p[c * 8];
        for (int i = 1; i < 8; i++) { float x = node_p[c * 8 + i]; if (x > bb) { bb = x; nact = i; } }
        float aw;
        { float sum = 0.f; for (int i = 0; i < 8; i++) sum += expf(node_p[c * 8 + i] - bb);
          aw = expf(node_p[c * 8 + nact] - bb) / sum; }

        // q selection: first 5 masked
        int qsel = 5; float qb = ep0[5];
        for (int i = 6; i < L; i++) if (ep0[i] > qb) { qb = ep0[i]; qsel = i; }
        float wq = selw_masked(ep0, L, 1, qsel);

        int ksel = -1, vsel = -1;
        float wk = 0.f, wv = 0.f;
        int ktype = 0;
        if (nact < 7) {
            int km = (nact > 0) ? 1 : 0;
            int start = km ? 5 : 0;
            ksel = start; float kb = ep1[start];
            for (int i = start + 1; i < L; i++) if (ep1[i] > kb) { kb = ep1[i]; ksel = i; }
            wk = selw_masked(ep1, L, km, ksel);
            ktype = (ksel / 5 == 0) ? -2 : -1;
            if (nact < 5) {
                if (nact == 0 && ktype == -2) {
                    vsel = 0; float vb = ep2[0];
                    for (int i = 1; i < 5; i++) if (ep2[i] > vb) { vb = ep2[i]; vsel = i; }
                    wv = selw_masked(ep2, 5, 0, vsel);
                } else {
                    int vm = km;
                    int vstart = vm ? 5 : 0;
                    vsel = vstart; float vb = ep2[vstart];
                    for (int i = vstart + 1; i < L; i++) if (ep2[i] > vb) { vb = ep2[i]; vsel = i; }
                    wv = selw_masked(ep2, L, vm, vsel);
                }
            }
        }

        // edge descriptors
        float* outc = g_outs[c];
        int inn;
        inn = fill_edge(c, 0, qsel, wq, lind, snode, bufs, edge_W, edge_b, edge_g, edge_beta, g_q);
        processed |= 1 << (inn + 2);
        if (nact < 7) {
            inn = fill_edge(c, 1, ksel, wk, lind, snode, bufs, edge_W, edge_b, edge_g, edge_beta, g_k);
            processed |= 1 << (inn + 2);
        }
        if (nact < 5) {
            inn = fill_edge(c, 2, vsel, wv, lind, snode, bufs, edge_W, edge_b, edge_g, edge_beta, g_v);
            processed |= 1 << (inn + 2);
        }

        // node descriptors
        const float* nw  = node_W + (size_t)c * 4 * D * D;
        const float* nbv = node_b + (size_t)c * 4 * D;
        const float* ngv = node_g + (size_t)c * D;
        const float* nbe = node_beta + (size_t)c * D;
        int s3 = c * 7 + 3, s4 = c * 7 + 4, s5 = c * 7 + 5, s6 = c * 7 + 6;

        if (nact == 0) {
            set_gd(s3, g_q, nw,             nbv,         1, ngv, nbe, 0, nullptr, nullptr, 1.f, g_t1, 0);
            set_gd(s4, g_k, nw + D * D,     nbv + D,     0, nullptr, nullptr, 0, nullptr, nullptr, 1.f, g_t2, 0);
            set_gd(s5, g_v, nw + 2 * D * D, nbv + 2 * D, 0, nullptr, nullptr, 0, nullptr, nullptr, 1.f, g_t3, 0);
            g_attn_on[c] = 1;
            set_gd(s6, g_t4, nw + 3 * D * D, nbv + 3 * D, 0, nullptr, nullptr, 0, nullptr, g_q, aw, outc, 0);
        } else if (nact == 1) {
            set_gd(s3, g_q, nw,         nbv,     0, nullptr, nullptr, 2, nullptr, nullptr, 1.f, g_t1, 0);
            set_gd(s4, g_k, nw + D * D, nbv + D, 0, nullptr, nullptr, 0, g_t1, nullptr, 1.f, g_t4, 0);
            set_gd(s6, g_t4, nw + 3 * D * D, nbv + 3 * D, 0, nullptr, nullptr, 0, nullptr, g_q, aw, outc, 0);
        } else if (nact == 3) {
            set_gd(s3, g_q, nw,             nullptr, 0, nullptr, nullptr, 0, nullptr, nullptr, 1.f, g_t1, 0);
            set_gd(s4, g_k, nw + D * D,     nullptr, 0, nullptr, nullptr, 0, nullptr, nullptr, 1.f, g_t1, 1);
            set_gd(s5, g_v, nw + 2 * D * D, nullptr, 0, nullptr, nullptr, 0, nullptr, nullptr, 1.f, g_t1, 1);
            set_gd(s6, g_t1, nw + 3 * D * D, nbv + 3 * D, 2, nullptr, nullptr, 0, nullptr, g_q, aw, outc, 0);
        } else if (nact == 5) {
            set_gd(s4, g_k, nw + D * D, nbv + D, 0, nullptr, nullptr, 2, nullptr, g_q, aw, outc, 0);
        } else { // 2, 4, 6, 7 elementwise
            ElemDesc& e = g_ed[c];
            e.active = 1; e.opcode = nact;
            e.q = g_q; e.k = g_k; e.v = g_v;
            e.g = ngv; e.b = nbe; e.scale = aw; e.dst = outc;
        }
        lind += nsrc;
    }
    int rem = 0;
    for (int n = 0; n < 8; n++)
        if (!((processed >> (n + 2)) & 1)) rem |= 1 << n;
    g_rem_mask = rem;
}

// ---------------- GEMM slot kernel: f32x2 packed FMA, double-buffered ----------------
// C[NTOK,D] = epi( pre(A)[NTOK,D] @ W[D,D] + bias ) (*mult)(+residual)(*scale)
__global__ __launch_bounds__(256) void gemm_slot(int slot) {
    GemmDesc d = g_gd[slot];
    if (!d.active) return;

    __shared__ float sA[2][BK][BM + 4];
    __shared__ float sW[2][BK][BN];
    __shared__ float s_mean[BM], s_rstd[BM];

    int tid = threadIdx.x;
    int m0 = blockIdx.y * BM;
    int n0 = blockIdx.x * BN;

    if (d.pre_mode == 1) {
        __shared__ float red_s[256], red_q[256];
        int r = tid >> 2, p = tid & 3;
        const float4* row = (const float4*)(d.A + (size_t)(m0 + r) * D + p * 128);
        float s = 0.f, q = 0.f;
        #pragma unroll
        for (int i = 0; i < 32; i++) {
            float4 v = row[i];
            s += v.x + v.y + v.z + v.w;
            q += v.x * v.x + v.y * v.y + v.z * v.z + v.w * v.w;
        }
        red_s[tid] = s; red_q[tid] = q;
        __syncthreads();
        if (p == 0) {
            float S = red_s[tid] + red_s[tid + 1] + red_s[tid + 2] + red_s[tid + 3];
            float Q = red_q[tid] + red_q[tid + 1] + red_q[tid + 2] + red_q[tid + 3];
            float m = S * (1.f / 512.f);
            float var = Q * (1.f / 512.f) - m * m;
            s_mean[r] = m; s_rstd[r] = rsqrtf(var + EPSf);
        }
        __syncthreads();
    }

    // load/store index mapping
    int arow = tid >> 2, akq = tid & 3;          // A: 64 rows x 4 float4 along K
    int wkr = tid >> 5, wnq = tid & 31;          // W: k rows 0..7 (+8), 32 float4 along N

    unsigned long long acc[4][4];
    #pragma unroll
    for (int i = 0; i < 4; i++)
        #pragma unroll
        for (int j = 0; j < 4; j++) acc[i][j] = 0ull;

    int ty = tid >> 4, tx = tid & 15;            // 4 rows x 8 cols per thread

    float4 la, lw0, lw1;

    // prologue: load tile 0
    {
        la  = *(const float4*)(d.A + (size_t)(m0 + arow) * D + akq * 4);
        lw0 = *(const float4*)(d.W + (size_t)(wkr) * D + n0 + wnq * 4);
        lw1 = *(const float4*)(d.W + (size_t)(wkr + 8) * D + n0 + wnq * 4);
    }

    for (int kt = 0; kt < D / BK; kt++) {
        int buf = kt & 1;
        // store staged regs into smem[buf]
        {
            float4 a = la;
            int kk = akq * 4;
            if (d.pre_mode == 1) {
                float m = s_mean[arow], rs = s_rstd[arow];
                int kb = kt * BK + kk;
                a.x = (a.x - m) * rs * d.lng[kb + 0] + d.lnb[kb + 0];
                a.y = (a.y - m) * rs * d.lng[kb + 1] + d.lnb[kb + 1];
                a.z = (a.z - m) * rs * d.lng[kb + 2] + d.lnb[kb + 2];
                a.w = (a.w - m) * rs * d.lng[kb + 3] + d.lnb[kb + 3];
            } else if (d.pre_mode == 2) {
                a.x = fmaxf(a.x, 0.f); a.y = fmaxf(a.y, 0.f);
                a.z = fmaxf(a.z, 0.f); a.w = fmaxf(a.w, 0.f);
            }
            sA[buf][kk + 0][arow] = a.x;
            sA[buf][kk + 1][arow] = a.y;
            sA[buf][kk + 2][arow] = a.z;
            sA[buf][kk + 3][arow] = a.w;
            *(float4*)&sW[buf][wkr][wnq * 4]     = lw0;
            *(float4*)&sW[buf][wkr + 8][wnq * 4] = lw1;
        }
        __syncthreads();
        // prefetch next tile into regs
        if (kt + 1 < D / BK) {
            int k0 = (kt + 1) * BK;
            la  = *(const float4*)(d.A + (size_t)(m0 + arow) * D + k0 + akq * 4);
            lw0 = *(const float4*)(d.W + (size_t)(k0 + wkr) * D + n0 + wnq * 4);
            lw1 = *(const float4*)(d.W + (size_t)(k0 + wkr + 8) * D + n0 + wnq * 4);
        }
        // compute on smem[buf]
        #pragma unroll
        for (int kk = 0; kk < BK; kk++) {
            float4 av = *(const float4*)&sA[buf][kk][ty * 4];
            float4 b0 = *(const float4*)&sW[buf][kk][tx * 8];
            float4 b1 = *(const float4*)&sW[buf][kk][tx * 8 + 4];
            unsigned long long aa0 = pack2(av.x, av.x);
            unsigned long long aa1 = pack2(av.y, av.y);
            unsigned long long aa2 = pack2(av.z, av.z);
            unsigned long long aa3 = pack2(av.w, av.w);
            unsigned long long bb0 = pack2(b0.x, b0.y);
            unsigned long long bb1 = pack2(b0.z, b0.w);
            unsigned long long bb2 = pack2(b1.x, b1.y);
            unsigned long long bb3 = pack2(b1.z, b1.w);
            fma2(acc[0][0], aa0, bb0); fma2(acc[0][1], aa0, bb1);
            fma2(acc[0][2], aa0, bb2); fma2(acc[0][3], aa0, bb3);
            fma2(acc[1][0], aa1, bb0); fma2(acc[1][1], aa1, bb1);
            fma2(acc[1][2], aa1, bb2); fma2(acc[1][3], aa1, bb3);
            fma2(acc[2][0], aa2, bb0); fma2(acc[2][1], aa2, bb1);
            fma2(acc[2][2], aa2, bb2); fma2(acc[2][3], aa2, bb3);
            fma2(acc[3][0], aa3, bb0); fma2(acc[3][1], aa3, bb1);
            fma2(acc[3][2], aa3, bb2); fma2(acc[3][3], aa3, bb3);
        }
        __syncthreads();
    }

    // epilogue
    #pragma unroll
    for (int i = 0; i < 4; i++) {
        int m = m0 + ty * 4 + i;
        float out[8];
        #pragma unroll
        for (int j = 0; j < 4; j++) {
            float2 v = unpack2(acc[i][j]);
            out[j * 2] = v.x; out[j * 2 + 1] = v.y;
        }
        #pragma unroll
        for (int j = 0; j < 8; j++) {
            int n = n0 + tx * 8 + j;
            float cv = out[j];
            if (d.bias) cv += d.bias[n];
            if (d.epi_act == 1) cv = fmaxf(cv, 0.f);
            else if (d.epi_act == 2) cv = gelu_f(cv);
            if (d.mult) cv *= d.mult[(size_t)m * D + n];
            if (d.residual) cv += d.residual[(size_t)m * D + n];
            cv *= d.scale;
            if (d.accumulate) cv += d.C[(size_t)m * D + n];
            out[j] = cv;
        }
        float* cp = d.C + (size_t)m * D + n0 + tx * 8;
        *(float4*)cp       = make_float4(out[0], out[1], out[2], out[3]);
        *(float4*)(cp + 4) = make_float4(out[4], out[5], out[6], out[7]);
    }
}

// ---------------- edge op4 copy-scale ----------------
__global__ void copy_slot(int slot) {
    CopyDesc d = g_cd[slot];
    if (!d.active) return;
    int i = blockIdx.x * blockDim.x + threadIdx.x;
    int stride = gridDim.x * blockDim.x;
    const float4* src = (const float4*)d.src;
    float4* dst = (float4*)d.dst;
    for (; i < NTOK * D / 4; i += stride) {
        float4 v = src[i];
        v.x *= d.scale; v.y *= d.scale; v.z *= d.scale; v.w *= d.scale;
        dst[i] = v;
    }
}

// ---------------- attention (act 0): one warp per query row, online softmax ------
__global__ __launch_bounds__(256) void attn_slot(int c) {
    if (!g_attn_on[c]) return;
    int warp = threadIdx.x >> 5, lane = threadIdx.x & 31;
    int bh = blockIdx.x;            // 0..31
    int b = bh >> 3, h = bh & 7;
    int s = blockIdx.y * 8 + warp;  // 0..1023

    const float* qrow = g_t1 + (size_t)((b << 10) + s) * D + h * 64 + lane * 2;
    float q0 = qrow[0], q1 = qrow[1];
    const float* kbase = g_t2 + (size_t)(b << 10) * D + h * 64 + lane * 2;
    const float* vbase = g_t3 + (size_t)(b << 10) * D + h * 64 + lane * 2;

    float m = -1e30f, l = 0.f, a0 = 0.f, a1 = 0.f;
    for (int sk = 0; sk < 1024; sk++) {
        float2 kk = *(const float2*)(kbase + (size_t)sk * D);
        float p = q0 * kk.x + q1 * kk.y;
        p += __shfl_xor_sync(0xFFFFFFFFu, p, 16);
        p += __shfl_xor_sync(0xFFFFFFFFu, p, 8);
        p += __shfl_xor_sync(0xFFFFFFFFu, p, 4);
        p += __shfl_xor_sync(0xFFFFFFFFu, p, 2);
        p += __shfl_xor_sync(0xFFFFFFFFu, p, 1);
        float dot = p * 0.125f;
        float mn = fmaxf(m, dot);
        float corr = __expf(m - mn);
        float w = __expf(dot - mn);
        float2 vv = *(const float2*)(vbase + (size_t)sk * D);
        l = l * corr + w;
        a0 = a0 * corr + w * vv.x;
        a1 = a1 * corr + w * vv.y;
        m = mn;
    }
    float inv = 1.f / l;
    float* orow = g_t4 + (size_t)((b << 10) + s) * D + h * 64 + lane * 2;
    orow[0] = a0 * inv;
    orow[1] = a1 * inv;
}

// ---------------- elementwise node ops (acts 2,4,6,7) ----------------
__global__ __launch_bounds__(256) void elem_node_kernel(int c) {
    ElemDesc d = g_ed[c];
    if (!d.active) return;
    int row = blockIdx.x;
    int tid = threadIdx.x;
    size_t base = (size_t)row * D;
    float x[2];
    #pragma unroll
    for (int i = 0; i < 2; i++) {
        int j = tid + i * 256;
        float qv = d.q[base + j];
        if (d.opcode == 2) x[i] = qv + d.k[base + j] + d.v[base + j];
        else if (d.opcode == 4) {
            float kv = d.k[base + j];
            x[i] = qv * (1.f / (1.f + expf(-kv))) + d.v[base + j];
        }
        else if (d.opcode == 6) x[i] = qv + d.k[base + j];
        else x[i] = qv; // 7
    }
    if (d.opcode == 2 || d.opcode == 7) {
        __shared__ float rs[256], rq[256];
        rs[tid] = x[0] + x[1];
        rq[tid] = x[0] * x[0] + x[1] * x[1];
        __syncthreads();
        for (int off = 128; off > 0; off >>= 1) {
            if (tid < off) { rs[tid] += rs[tid + off]; rq[tid] += rq[tid + off]; }
            __syncthreads();
        }
        float mean = rs[0] * (1.f / 512.f);
        float var = rq[0] * (1.f / 512.f) - mean * mean;
        float rstd = rsqrtf(var + EPSf);
        #pragma unroll
        for (int i = 0; i < 2; i++) {
            int j = tid + i * 256;
            d.dst[base + j] = d.scale * ((x[i] - mean) * rstd * d.g[j] + d.b[j]);
        }
    } else {
        #pragma unroll
        for (int i = 0; i < 2; i++) {
            int j = tid + i * 256;
            d.dst[base + j] = d.scale * x[i];
        }
    }
}

// ---------------- final: sum remaining outs + LayerNorm ----------------
__global__ __launch_bounds__(256) void final_kernel(const float* out_g, const float* out_beta,
                                                    float* out) {
    int row = blockIdx.x;
    int tid = threadIdx.x;
    int mask = g_rem_mask;
    size_t base = (size_t)row * D;
    float x[2];
    #pragma unroll
    for (int i = 0; i < 2; i++) {
        int j = tid + i * 256;
        float s = 0.f;
        for (int n = 0; n < 8; n++)
            if ((mask >> n) & 1) s += g_outs[n][base + j];
        x[i] = s;
    }
    __shared__ float rs[256], rq[256];
    rs[tid] = x[0] + x[1];
    rq[tid] = x[0] * x[0] + x[1] * x[1];
    __syncthreads();
    for (int off = 128; off > 0; off >>= 1) {
        if (tid < off) { rs[tid] += rs[tid + off]; rq[tid] += rq[tid + off]; }
        __syncthreads();
    }
    float mean = rs[0] * (1.f / 512.f);
    float var = rq[0] * (1.f / 512.f) - mean * mean;
    float rstd = rsqrtf(var + EPSf);
    #pragma unroll
    for (int i = 0; i < 2; i++) {
        int j = tid + i * 256;
        out[base + j] = (x[i] - mean) * rstd * out_g[j] + out_beta[j];
    }
}

// ---------------- launch ----------------
extern "C" void kernel_launch(void* const* d_in, const int* in_sizes, int n_in,
                              void* d_out, int out_size) {
    const float* inpute   = (const float*)d_in[0];
    const float* inputo   = (const float*)d_in[1];
    const float* node_p   = (const float*)d_in[2];
    const float* edge_p   = (const float*)d_in[3];
    const float* edge_W   = (const float*)d_in[4];
    const float* edge_b   = (const float*)d_in[5];
    const float* edge_g   = (const float*)d_in[6];
    const float* edge_bet = (const float*)d_in[7];
    const float* node_W   = (const float*)d_in[8];
    const float* node_b   = (const float*)d_in[9];
    const float* node_g   = (const float*)d_in[10];
    const float* node_bet = (const float*)d_in[11];
    const float* out_g    = (const float*)d_in[12];
    const float* out_bet  = (const float*)d_in[13];
    float* out = (float*)d_out;

    routing_kernel<<<1, 1>>>(inpute, inputo, node_p, edge_p,
                             edge_W, edge_b, edge_g, edge_bet,
                             node_W, node_b, node_g, node_bet);

    dim3 ggrid(D / BN, NTOK / BM);   // (4, 64)
    for (int c = 0; c < 8; c++) {
        for (int w = 0; w < 3; w++) {
            gemm_slot<<<ggrid, 256>>>(c * 7 + w);
            copy_slot<<<512, 256>>>(c * 3 + w);
        }
        gemm_slot<<<ggrid, 256>>>(c * 7 + 3);
        gemm_slot<<<ggrid, 256>>>(c * 7 + 4);
        gemm_slot<<<ggrid, 256>>>(c * 7 + 5);
        attn_slot<<<dim3(32, 128), 256>>>(c);
        gemm_slot<<<ggrid, 256>>>(c * 7 + 6);
        elem_node_kernel<<<NTOK, 256>>>(c);
    }
    final_kernel<<<NTOK, 256>>>(out_g, out_bet, out);
}

// round 4
// speedup vs baseline: 2.9757x; 1.2491x over previous
#include <cuda_runtime.h>
#include <cuda_bf16.h>
#include <math.h>
#include <stdint.h>

#define D       512
#define NTOK    4096      // B*SLEN = 4*1024
#define NNODn   8
#define NEDGEn  34
#define EPSf    1e-6f

// GEMM tile
#define BM 128
#define BN 64
#define BK 16

// ---------------- scratch buffers (device globals; no allocation allowed) ----------
__device__ float g_outs[8][NTOK * D];
__device__ float g_q[NTOK * D];
__device__ float g_k[NTOK * D];
__device__ float g_v[NTOK * D];
__device__ float g_t1[NTOK * D];
__device__ float g_t2[NTOK * D];
__device__ float g_t3[NTOK * D];
__device__ float g_t4[NTOK * D];

// ---------------- descriptors ----------------
struct GemmDesc {
    int active;
    int pre_mode;    // 0 none, 1 LN(A), 2 relu(A)
    int epi_act;     // 0 none, 1 relu, 2 gelu
    int accumulate;  // 1: C += result
    const float *A, *W, *bias, *lng, *lnb, *mult, *residual;
    float scale;
    float *C;
};
struct CopyDesc { int active; const float* src; float* dst; float scale; };
struct ElemDesc {
    int active; int opcode;   // 2,4,6,7
    const float *q, *k, *v, *g, *b;
    float scale; float* dst;
};

__device__ GemmDesc g_gd[56];   // node*7 + {EQ,EK,EV,G1,G2,G3,G4}
__device__ CopyDesc g_cd[24];   // node*3 + {q,k,v}
__device__ ElemDesc g_ed[8];
__device__ int g_attn_on[8];
__device__ int g_rem_mask;

// ---------------- tf32 helpers ----------------
__device__ __forceinline__ float2 split_tf32(float x) {
    uint32_t hi;
    asm("cvt.rna.tf32.f32 %0, %1;" : "=r"(hi) : "f"(x));
    float hf = __uint_as_float(hi);
    float lo = x - hf;
    uint32_t lb;
    asm("cvt.rna.tf32.f32 %0, %1;" : "=r"(lb) : "f"(lo));
    return make_float2(hf, __uint_as_float(lb));
}

__device__ __forceinline__ void mma_tf32(float* c, const uint32_t* a, const uint32_t* b) {
    asm volatile(
        "mma.sync.aligned.m16n8k8.row.col.f32.tf32.tf32.f32 "
        "{%0,%1,%2,%3}, {%4,%5,%6,%7}, {%8,%9}, {%0,%1,%2,%3};"
        : "+f"(c[0]), "+f"(c[1]), "+f"(c[2]), "+f"(c[3])
        : "r"(a[0]), "r"(a[1]), "r"(a[2]), "r"(a[3]),
          "r"(b[0]), "r"(b[1]));
}

// ---------------- small helpers ----------------
__device__ __forceinline__ float gelu_f(float x) {
    const float k0 = 0.7978845608028654f;
    float x3 = x * x * x;
    return 0.5f * x * (1.f + tanhf(k0 * (x + 0.044715f * x3)));
}

__device__ float selw_masked(const float* l, int L, int mask5, int sel) {
    float mx = -1e30f;
    for (int i = 0; i < L; i++) { if (mask5 && i < 5) continue; if (l[i] > mx) mx = l[i]; }
    float s = 0.f;
    for (int i = 0; i < L; i++) { if (mask5 && i < 5) continue; s += expf(l[i] - mx); }
    return expf(l[sel] - mx) / s;
}

__device__ void set_gd(int slot, const float* A, const float* W, const float* bias,
                       int pre, const float* lng, const float* lnb,
                       int epi, const float* mult, const float* residual,
                       float scale, float* C, int accum) {
    GemmDesc& g = g_gd[slot];
    g.active = 1; g.A = A; g.W = W; g.bias = bias;
    g.pre_mode = pre; g.lng = lng; g.lnb = lnb;
    g.epi_act = epi; g.mult = mult; g.residual = residual;
    g.scale = scale; g.C = C; g.accumulate = accum;
}

// Fill an edge slot; returns consumed input node index inn (-2..7)
__device__ int fill_edge(int node, int which, int sel, float w, int lind, int snode,
                         const float* const* bufs,
                         const float* eW, const float* eb, const float* eg, const float* ebe,
                         float* dst) {
    int se = sel / 5, op = sel % 5;
    int inn = (se == 0) ? -2 : (snode + se);
    int e = lind + se;
    const float* src = bufs[inn + 2];
    if (op == 4) {
        CopyDesc& cd = g_cd[node * 3 + which];
        cd.active = 1; cd.src = src; cd.dst = dst; cd.scale = w;
    } else {
        set_gd(node * 7 + which,
               src, eW + (size_t)e * D * D, eb + e * D,
               (op <= 2) ? 1 : 0, eg + e * D, ebe + e * D,
               (op == 0) ? 1 : ((op == 1) ? 2 : 0),
               nullptr, nullptr, w, dst, 0);
    }
    return inn;
}

// ---------------- routing kernel: computes routes + writes all descriptors ----------
__global__ void routing_kernel(const float* inpute, const float* inputo,
                               const float* node_p, const float* edge_p,
                               const float* edge_W, const float* edge_b,
                               const float* edge_g, const float* edge_beta,
                               const float* node_W, const float* node_b,
                               const float* node_g, const float* node_beta) {
    if (threadIdx.x != 0 || blockIdx.x != 0) return;

    const float* bufs[10];
    bufs[0] = inpute; bufs[1] = inputo;
    for (int i = 0; i < 8; i++) bufs[2 + i] = g_outs[i];

    for (int i = 0; i < 56; i++) g_gd[i].active = 0;
    for (int i = 0; i < 24; i++) g_cd[i].active = 0;
    for (int i = 0; i < 8; i++) { g_ed[i].active = 0; g_attn_on[i] = 0; }

    int processed = 0;
    int lind = 0;
    for (int c = 0; c < 8; c++) {
        int nsrc = (c + 2 < 5) ? (c + 2) : 5;
        int snode = c - nsrc;
        int L = nsrc * 5;
        float ep0[25], ep1[25], ep2[25];
        for (int s = 0; s < nsrc; s++)
            for (int j = 0; j < 5; j++) {
                int e = lind + s;
                ep0[s * 5 + j] = edge_p[(0 * NEDGEn + e) * 5 + j];
                ep1[s * 5 + j] = edge_p[(1 * NEDGEn + e) * 5 + j];
                ep2[s * 5 + j] = edge_p[(2 * NEDGEn + e) * 5 + j];
            }
        // node activation argmax + softmax weight
        int nact = 0; float bb = node_p[c * 8];
        for (int i = 1; i < 8; i++) { float x = node_p[c * 8 + i]; if (x > bb) { bb = x; nact = i; } }
        float aw;
        { float sum = 0.f; for (int i = 0; i < 8; i++) sum += expf(node_p[c * 8 + i] - bb);
          aw = expf(node_p[c * 8 + nact] - bb) / sum; }

        // q selection: first 5 masked
        int qsel = 5; float qb = ep0[5];
        for (int i = 6; i < L; i++) if (ep0[i] > qb) { qb = ep0[i]; qsel = i; }
        float wq = selw_masked(ep0, L, 1, qsel);

        int ksel = -1, vsel = -1;
        float wk = 0.f, wv = 0.f;
        int ktype = 0;
        if (nact < 7) {
            int km = (nact > 0) ? 1 : 0;
            int start = km ? 5 : 0;
            ksel = start; float kb = ep1[start];
            for (int i = start + 1; i < L; i++) if (ep1[i] > kb) { kb = ep1[i]; ksel = i; }
            wk = selw_masked(ep1, L, km, ksel);
            ktype = (ksel / 5 == 0) ? -2 : -1;
            if (nact < 5) {
                if (nact == 0 && ktype == -2) {
                    vsel = 0; float vb = ep2[0];
                    for (int i = 1; i < 5; i++) if (ep2[i] > vb) { vb = ep2[i]; vsel = i; }
                    wv = selw_masked(ep2, 5, 0, vsel);
                } else {
                    int vm = km;
                    int vstart = vm ? 5 : 0;
                    vsel = vstart; float vb = ep2[vstart];
                    for (int i = vstart + 1; i < L; i++) if (ep2[i] > vb) { vb = ep2[i]; vsel = i; }
                    wv = selw_masked(ep2, L, vm, vsel);
                }
            }
        }

        // edge descriptors
        float* outc = g_outs[c];
        int inn;
        inn = fill_edge(c, 0, qsel, wq, lind, snode, bufs, edge_W, edge_b, edge_g, edge_beta, g_q);
        processed |= 1 << (inn + 2);
        if (nact < 7) {
            inn = fill_edge(c, 1, ksel, wk, lind, snode, bufs, edge_W, edge_b, edge_g, edge_beta, g_k);
            processed |= 1 << (inn + 2);
        }
        if (nact < 5) {
            inn = fill_edge(c, 2, vsel, wv, lind, snode, bufs, edge_W, edge_b, edge_g, edge_beta, g_v);
            processed |= 1 << (inn + 2);
        }

        // node descriptors
        const float* nw  = node_W + (size_t)c * 4 * D * D;
        const float* nbv = node_b + (size_t)c * 4 * D;
        const float* ngv = node_g + (size_t)c * D;
        const float* nbe = node_beta + (size_t)c * D;
        int s3 = c * 7 + 3, s4 = c * 7 + 4, s5 = c * 7 + 5, s6 = c * 7 + 6;

        if (nact == 0) {
            set_gd(s3, g_q, nw,             nbv,         1, ngv, nbe, 0, nullptr, nullptr, 1.f, g_t1, 0);
            set_gd(s4, g_k, nw + D * D,     nbv + D,     0, nullptr, nullptr, 0, nullptr, nullptr, 1.f, g_t2, 0);
            set_gd(s5, g_v, nw + 2 * D * D, nbv + 2 * D, 0, nullptr, nullptr, 0, nullptr, nullptr, 1.f, g_t3, 0);
            g_attn_on[c] = 1;
            set_gd(s6, g_t4, nw + 3 * D * D, nbv + 3 * D, 0, nullptr, nullptr, 0, nullptr, g_q, aw, outc, 0);
        } else if (nact == 1) {
            set_gd(s3, g_q, nw,         nbv,     0, nullptr, nullptr, 2, nullptr, nullptr, 1.f, g_t1, 0);
            set_gd(s4, g_k, nw + D * D, nbv + D, 0, nullptr, nullptr, 0, g_t1, nullptr, 1.f, g_t4, 0);
            set_gd(s6, g_t4, nw + 3 * D * D, nbv + 3 * D, 0, nullptr, nullptr, 0, nullptr, g_q, aw, outc, 0);
        } else if (nact == 3) {
            set_gd(s3, g_q, nw,             nullptr, 0, nullptr, nullptr, 0, nullptr, nullptr, 1.f, g_t1, 0);
            set_gd(s4, g_k, nw + D * D,     nullptr, 0, nullptr, nullptr, 0, nullptr, nullptr, 1.f, g_t1, 1);
            set_gd(s5, g_v, nw + 2 * D * D, nullptr, 0, nullptr, nullptr, 0, nullptr, nullptr, 1.f, g_t1, 1);
            set_gd(s6, g_t1, nw + 3 * D * D, nbv + 3 * D, 2, nullptr, nullptr, 0, nullptr, g_q, aw, outc, 0);
        } else if (nact == 5) {
            set_gd(s4, g_k, nw + D * D, nbv + D, 0, nullptr, nullptr, 2, nullptr, g_q, aw, outc, 0);
        } else { // 2, 4, 6, 7 elementwise
            ElemDesc& e = g_ed[c];
            e.active = 1; e.opcode = nact;
            e.q = g_q; e.k = g_k; e.v = g_v;
            e.g = ngv; e.b = nbe; e.scale = aw; e.dst = outc;
        }
        lind += nsrc;
    }
    int rem = 0;
    for (int n = 0; n < 8; n++)
        if (!((processed >> (n + 2)) & 1)) rem |= 1 << n;
    g_rem_mask = rem;
}

// ---------------- GEMM slot kernel: tf32 tensor cores, 3-product split precision ----
// C[NTOK,D] = epi( pre(A)[NTOK,D] @ W[D,D] + bias ) (*mult)(+residual)(*scale)
// BM=128, BN=64, BK=16; 8 warps as 4(M) x 2(N); warp tile 32x32 = 2 m16 x 4 n8 mmas.
__global__ __launch_bounds__(256) void gemm_slot(int slot) {
    GemmDesc d = g_gd[slot];
    if (!d.active) return;

    __shared__ float2 sA2[BK][BM + 4];   // [k][m] {hi,lo}; row stride 132 f2 -> 8-bank offset
    __shared__ float2 sW2[BK][BN + 4];   // [k][n] {hi,lo}; row stride 68 f2 -> 8-bank offset
    __shared__ float s_mean[BM], s_rstd[BM];

    int tid = threadIdx.x;
    int m0 = blockIdx.y * BM;
    int n0 = blockIdx.x * BN;

    if (d.pre_mode == 1) {
        __shared__ float red_s[256], red_q[256];
        int r = tid >> 1, p = tid & 1;
        const float4* row = (const float4*)(d.A + (size_t)(m0 + r) * D + p * 256);
        float s = 0.f, q = 0.f;
        #pragma unroll
        for (int i = 0; i < 64; i++) {
            float4 v = row[i];
            s += v.x + v.y + v.z + v.w;
            q += v.x * v.x + v.y * v.y + v.z * v.z + v.w * v.w;
        }
        red_s[tid] = s; red_q[tid] = q;
        __syncthreads();
        if (p == 0) {
            float S = red_s[tid] + red_s[tid + 1];
            float Q = red_q[tid] + red_q[tid + 1];
            float m = S * (1.f / 512.f);
            float var = Q * (1.f / 512.f) - m * m;
            s_mean[r] = m; s_rstd[r] = rsqrtf(var + EPSf);
        }
        __syncthreads();
    }

    int warp = tid >> 5, lane = tid & 31;
    int g = lane >> 2, t = lane & 3;
    int wM = (warp >> 1) * 32;    // 4 warps along M
    int wN = (warp & 1) * 32;     // 2 warps along N

    // staging mappings
    int arow = tid & 127;          // A row within tile
    int akq0 = (tid >> 7) * 2;     // A float4-quad base (0 or 2); +i covers 0..3
    int wk = tid >> 4;             // W k row 0..15
    int wnq = tid & 15;            // W float4 col quad

    float acc[2][4][4];
    #pragma unroll
    for (int a = 0; a < 2; a++)
        #pragma unroll
        for (int b = 0; b < 4; b++)
            #pragma unroll
            for (int cc = 0; cc < 4; cc++) acc[a][b][cc] = 0.f;

    float4 aval[2];
    float4 wval;
    aval[0] = *(const float4*)(d.A + (size_t)(m0 + arow) * D + akq0 * 4);
    aval[1] = *(const float4*)(d.A + (size_t)(m0 + arow) * D + akq0 * 4 + 4);
    wval    = *(const float4*)(d.W + (size_t)wk * D + n0 + wnq * 4);

    for (int kt = 0; kt < D / BK; kt++) {
        // transform + split + store to smem
        {
            float mn = 0.f, rs = 0.f;
            if (d.pre_mode == 1) { mn = s_mean[arow]; rs = s_rstd[arow]; }
            #pragma unroll
            for (int i = 0; i < 2; i++) {
                float4 a = aval[i];
                int kk = (akq0 + i) * 4;
                int kg = kt * BK + kk;
                if (d.pre_mode == 1) {
                    a.x = (a.x - mn) * rs * d.lng[kg + 0] + d.lnb[kg + 0];
                    a.y = (a.y - mn) * rs * d.lng[kg + 1] + d.lnb[kg + 1];
                    a.z = (a.z - mn) * rs * d.lng[kg + 2] + d.lnb[kg + 2];
                    a.w = (a.w - mn) * rs * d.lng[kg + 3] + d.lnb[kg + 3];
                } else if (d.pre_mode == 2) {
                    a.x = fmaxf(a.x, 0.f); a.y = fmaxf(a.y, 0.f);
                    a.z = fmaxf(a.z, 0.f); a.w = fmaxf(a.w, 0.f);
                }
                sA2[kk + 0][arow] = split_tf32(a.x);
                sA2[kk + 1][arow] = split_tf32(a.y);
                sA2[kk + 2][arow] = split_tf32(a.z);
                sA2[kk + 3][arow] = split_tf32(a.w);
            }
            float4 w = wval;
            sW2[wk][wnq * 4 + 0] = split_tf32(w.x);
            sW2[wk][wnq * 4 + 1] = split_tf32(w.y);
            sW2[wk][wnq * 4 + 2] = split_tf32(w.z);
            sW2[wk][wnq * 4 + 3] = split_tf32(w.w);
        }
        __syncthreads();
        // prefetch next tile
        if (kt + 1 < D / BK) {
            int kb = (kt + 1) * BK;
            aval[0] = *(const float4*)(d.A + (size_t)(m0 + arow) * D + kb + akq0 * 4);
            aval[1] = *(const float4*)(d.A + (size_t)(m0 + arow) * D + kb + akq0 * 4 + 4);
            wval    = *(const float4*)(d.W + (size_t)(kb + wk) * D + n0 + wnq * 4);
        }
        // compute: 2 k8 steps
        #pragma unroll
        for (int k8 = 0; k8 < 2; k8++) {
            uint32_t ahi[2][4], alo[2][4], bhi[4][2], blo[4][2];
            #pragma unroll
            for (int mt = 0; mt < 2; mt++) {
                const float2* p  = &sA2[k8 * 8 + t][wM + mt * 16 + g];
                const float2* p4 = &sA2[k8 * 8 + t + 4][wM + mt * 16 + g];
                float2 v0 = p[0], v1 = p[8], v2 = p4[0], v3 = p4[8];
                ahi[mt][0] = __float_as_uint(v0.x); alo[mt][0] = __float_as_uint(v0.y);
                ahi[mt][1] = __float_as_uint(v1.x); alo[mt][1] = __float_as_uint(v1.y);
                ahi[mt][2] = __float_as_uint(v2.x); alo[mt][2] = __float_as_uint(v2.y);
                ahi[mt][3] = __float_as_uint(v3.x); alo[mt][3] = __float_as_uint(v3.y);
            }
            #pragma unroll
            for (int nt = 0; nt < 4; nt++) {
                float2 w0 = sW2[k8 * 8 + t][wN + nt * 8 + g];
                float2 w1 = sW2[k8 * 8 + t + 4][wN + nt * 8 + g];
                bhi[nt][0] = __float_as_uint(w0.x); blo[nt][0] = __float_as_uint(w0.y);
                bhi[nt][1] = __float_as_uint(w1.x); blo[nt][1] = __float_as_uint(w1.y);
            }
            #pragma unroll
            for (int mt = 0; mt < 2; mt++)
                #pragma unroll
                for (int nt = 0; nt < 4; nt++) {
                    mma_tf32(acc[mt][nt], ahi[mt], bhi[nt]);
                    mma_tf32(acc[mt][nt], ahi[mt], blo[nt]);
                    mma_tf32(acc[mt][nt], alo[mt], bhi[nt]);
                }
        }
        __syncthreads();
    }

    // epilogue
    #pragma unroll
    for (int mt = 0; mt < 2; mt++)
        #pragma unroll
        for (int nt = 0; nt < 4; nt++) {
            int m = m0 + wM + mt * 16 + g;
            int n = n0 + wN + nt * 8 + 2 * t;
            float b0v = 0.f, b1v = 0.f;
            if (d.bias) { b0v = d.bias[n]; b1v = d.bias[n + 1]; }
            #pragma unroll
            for (int rr = 0; rr < 2; rr++) {
                int mr = m + rr * 8;
                float x0 = acc[mt][nt][rr * 2 + 0] + b0v;
                float x1 = acc[mt][nt][rr * 2 + 1] + b1v;
                if (d.epi_act == 1) { x0 = fmaxf(x0, 0.f); x1 = fmaxf(x1, 0.f); }
                else if (d.epi_act == 2) { x0 = gelu_f(x0); x1 = gelu_f(x1); }
                if (d.mult) {
                    float2 mv = *(const float2*)(d.mult + (size_t)mr * D + n);
                    x0 *= mv.x; x1 *= mv.y;
                }
                if (d.residual) {
                    float2 rv = *(const float2*)(d.residual + (size_t)mr * D + n);
                    x0 += rv.x; x1 += rv.y;
                }
                x0 *= d.scale; x1 *= d.scale;
                if (d.accumulate) {
                    float2 cv = *(const float2*)(d.C + (size_t)mr * D + n);
                    x0 += cv.x; x1 += cv.y;
                }
                *(float2*)(d.C + (size_t)mr * D + n) = make_float2(x0, x1);
            }
        }
}

// ---------------- edge op4 copy-scale ----------------
__global__ void copy_slot(int slot) {
    CopyDesc d = g_cd[slot];
    if (!d.active) return;
    int i = blockIdx.x * blockDim.x + threadIdx.x;
    int stride = gridDim.x * blockDim.x;
    const float4* src = (const float4*)d.src;
    float4* dst = (float4*)d.dst;
    for (; i < NTOK * D / 4; i += stride) {
        float4 v = src[i];
        v.x *= d.scale; v.y *= d.scale; v.z *= d.scale; v.w *= d.scale;
        dst[i] = v;
    }
}

// ---------------- attention (act 0): one warp per query row, online softmax ------
__global__ __launch_bounds__(256) void attn_slot(int c) {
    if (!g_attn_on[c]) return;
    int warp = threadIdx.x >> 5, lane = threadIdx.x & 31;
    int bh = blockIdx.x;            // 0..31
    int b = bh >> 3, h = bh & 7;
    int s = blockIdx.y * 8 + warp;  // 0..1023

    const float* qrow = g_t1 + (size_t)((b << 10) + s) * D + h * 64 + lane * 2;
    float q0 = qrow[0], q1 = qrow[1];
    const float* kbase = g_t2 + (size_t)(b << 10) * D + h * 64 + lane * 2;
    const float* vbase = g_t3 + (size_t)(b << 10) * D + h * 64 + lane * 2;

    float m = -1e30f, l = 0.f, a0 = 0.f, a1 = 0.f;
    for (int sk = 0; sk < 1024; sk++) {
        float2 kk = *(const float2*)(kbase + (size_t)sk * D);
        float p = q0 * kk.x + q1 * kk.y;
        p += __shfl_xor_sync(0xFFFFFFFFu, p, 16);
        p += __shfl_xor_sync(0xFFFFFFFFu, p, 8);
        p += __shfl_xor_sync(0xFFFFFFFFu, p, 4);
        p += __shfl_xor_sync(0xFFFFFFFFu, p, 2);
        p += __shfl_xor_sync(0xFFFFFFFFu, p, 1);
        float dot = p * 0.125f;
        float mn = fmaxf(m, dot);
        float corr = __expf(m - mn);
        float w = __expf(dot - mn);
        float2 vv = *(const float2*)(vbase + (size_t)sk * D);
        l = l * corr + w;
        a0 = a0 * corr + w * vv.x;
        a1 = a1 * corr + w * vv.y;
        m = mn;
    }
    float inv = 1.f / l;
    float* orow = g_t4 + (size_t)((b << 10) + s) * D + h * 64 + lane * 2;
    orow[0] = a0 * inv;
    orow[1] = a1 * inv;
}

// ---------------- elementwise node ops (acts 2,4,6,7) ----------------
__global__ __launch_bounds__(256) void elem_node_kernel(int c) {
    ElemDesc d = g_ed[c];
    if (!d.active) return;
    int row = blockIdx.x;
    int tid = threadIdx.x;
    size_t base = (size_t)row * D;
    float x[2];
    #pragma unroll
    for (int i = 0; i < 2; i++) {
        int j = tid + i * 256;
        float qv = d.q[base + j];
        if (d.opcode == 2) x[i] = qv + d.k[base + j] + d.v[base + j];
        else if (d.opcode == 4) {
            float kv = d.k[base + j];
            x[i] = qv * (1.f / (1.f + expf(-kv))) + d.v[base + j];
        }
        else if (d.opcode == 6) x[i] = qv + d.k[base + j];
        else x[i] = qv; // 7
    }
    if (d.opcode == 2 || d.opcode == 7) {
        __shared__ float rs[256], rq[256];
        rs[tid] = x[0] + x[1];
        rq[tid] = x[0] * x[0] + x[1] * x[1];
        __syncthreads();
        for (int off = 128; off > 0; off >>= 1) {
            if (tid < off) { rs[tid] += rs[tid + off]; rq[tid] += rq[tid + off]; }
            __syncthreads();
        }
        float mean = rs[0] * (1.f / 512.f);
        float var = rq[0] * (1.f / 512.f) - mean * mean;
        float rstd = rsqrtf(var + EPSf);
        #pragma unroll
        for (int i = 0; i < 2; i++) {
            int j = tid + i * 256;
            d.dst[base + j] = d.scale * ((x[i] - mean) * rstd * d.g[j] + d.b[j]);
        }
    } else {
        #pragma unroll
        for (int i = 0; i < 2; i++) {
            int j = tid + i * 256;
            d.dst[base + j] = d.scale * x[i];
        }
    }
}

// ---------------- final: sum remaining outs + LayerNorm ----------------
__global__ __launch_bounds__(256) void final_kernel(const float* out_g, const float* out_beta,
                                                    float* out) {
    int row = blockIdx.x;
    int tid = threadIdx.x;
    int mask = g_rem_mask;
    size_t base = (size_t)row * D;
    float x[2];
    #pragma unroll
    for (int i = 0; i < 2; i++) {
        int j = tid + i * 256;
        float s = 0.f;
        for (int n = 0; n < 8; n++)
            if ((mask >> n) & 1) s += g_outs[n][base + j];
        x[i] = s;
    }
    __shared__ float rs[256], rq[256];
    rs[tid] = x[0] + x[1];
    rq[tid] = x[0] * x[0] + x[1] * x[1];
    __syncthreads();
    for (int off = 128; off > 0; off >>= 1) {
        if (tid < off) { rs[tid] += rs[tid + off]; rq[tid] += rq[tid + off]; }
        __syncthreads();
    }
    float mean = rs[0] * (1.f / 512.f);
    float var = rq[0] * (1.f / 512.f) - mean * mean;
    float rstd = rsqrtf(var + EPSf);
    #pragma unroll
    for (int i = 0; i < 2; i++) {
        int j = tid + i * 256;
        out[base + j] = (x[i] - mean) * rstd * out_g[j] + out_beta[j];
    }
}

// ---------------- launch ----------------
extern "C" void kernel_launch(void* const* d_in, const int* in_sizes, int n_in,
                              void* d_out, int out_size) {
    const float* inpute   = (const float*)d_in[0];
    const float* inputo   = (const float*)d_in[1];
    const float* node_p   = (const float*)d_in[2];
    const float* edge_p   = (const float*)d_in[3];
    const float* edge_W   = (const float*)d_in[4];
    const float* edge_b   = (const float*)d_in[5];
    const float* edge_g   = (const float*)d_in[6];
    const float* edge_bet = (const float*)d_in[7];
    const float* node_W   = (const float*)d_in[8];
    const float* node_b   = (const float*)d_in[9];
    const float* node_g   = (const float*)d_in[10];
    const float* node_bet = (const float*)d_in[11];
    const float* out_g    = (const float*)d_in[12];
    const float* out_bet  = (const float*)d_in[13];
    float* out = (float*)d_out;

    routing_kernel<<<1, 1>>>(inpute, inputo, node_p, edge_p,
                             edge_W, edge_b, edge_g, edge_bet,
                             node_W, node_b, node_g, node_bet);

    dim3 ggrid(D / BN, NTOK / BM);   // (8, 32)
    for (int c = 0; c < 8; c++) {
        for (int w = 0; w < 3; w++) {
            gemm_slot<<<ggrid, 256>>>(c * 7 + w);
            copy_slot<<<512, 256>>>(c * 3 + w);
        }
        gemm_slot<<<ggrid, 256>>>(c * 7 + 3);
        gemm_slot<<<ggrid, 256>>>(c * 7 + 4);
        gemm_slot<<<ggrid, 256>>>(c * 7 + 5);
        attn_slot<<<dim3(32, 128), 256>>>(c);
        gemm_slot<<<ggrid, 256>>>(c * 7 + 6);
        elem_node_kernel<<<NTOK, 256>>>(c);
    }
    final_kernel<<<NTOK, 256>>>(out_g, out_bet, out);
}